// round 11
// baseline (speedup 1.0000x reference)
#include <cuda_runtime.h>

// ODEINDLayer: 256 independent SPD block-tridiagonal systems (100 blocks of
// 3x3). RADIX-4 parallel cyclic reduction, pure fp32: level 0 fused into
// registers, then 3 barrier phases each performing TWO PCR levels (thread t
// recomputes neighbor states t+-2s locally from published level-l data).
// One CTA per system, one thread per node.

#define NSYS 256
#define NT   100

__device__ __forceinline__ float frcp_nr(float x) {
    float r; asm("rcp.approx.f32 %0, %1;" : "=f"(r) : "f"(x));
    return r * (2.0f - x * r);
}

// Inverse of symmetric 3x3 (packed 00,01,02,11,12,22).
__device__ __forceinline__ void inv3_sym(const float M[6], float I[6]) {
    float A00 = M[3]*M[5] - M[4]*M[4];
    float A01 = M[2]*M[4] - M[1]*M[5];
    float A02 = M[1]*M[4] - M[2]*M[3];
    float A11 = M[0]*M[5] - M[2]*M[2];
    float A12 = M[1]*M[2] - M[0]*M[4];
    float A22 = M[0]*M[3] - M[1]*M[1];
    float id  = frcp_nr(M[0]*A00 + M[1]*A01 + M[2]*A02);
    I[0]=A00*id; I[1]=A01*id; I[2]=A02*id; I[3]=A11*id; I[4]=A12*id; I[5]=A22*id;
}

// Build node i's initial blocks from inputs (closed forms).
__device__ __forceinline__ void build_node(int i,
        const float* __restrict__ C, const float* __restrict__ R,
        const float* __restrict__ IV, const float* __restrict__ ST,
        float D[6], float U[9], float B[3])
{
    float c0 = C[3*i], c1 = C[3*i+1], c2 = C[3*i+2];
    float rt = R[i];
    D[0]=c0*c0; D[1]=c0*c1; D[2]=c0*c2; D[3]=c1*c1; D[4]=c1*c2; D[5]=c2*c2;
    B[0]=c0*rt; B[1]=c1*rt; B[2]=c2*rt;
    if (i == 0) { D[0] += 1.0f; D[3] += 1.0f; B[0] += IV[0]; B[1] += IV[1]; }
    if (i < 99) {
        float h = ST[i], h2 = h*h;
        D[0] += 2.0f;      D[1] += h;                D[2] += 0.5f*h2;
        D[3] += h2+3.0f;   D[4] += h*(0.5f*h2+1.5f); D[5] += h2*(0.25f*h2+1.25f);
        U[0]=-2.0f;    U[1]=h;       U[2]=-0.5f*h2;
        U[3]=-h;       U[4]=-3.0f;   U[5]=1.5f*h;
        U[6]=-0.5f*h2; U[7]=-1.5f*h; U[8]=0.25f*h2;
    } else {
        #pragma unroll
        for (int k = 0; k < 9; ++k) U[k] = 0.0f;
    }
    if (i >= 1) {
        float g = ST[i-1], g2 = g*g;
        D[0] += 2.0f;      D[1] -= g;                D[2] += 0.5f*g2;
        D[3] += g2+3.0f;   D[4] -= g*(0.5f*g2+1.5f); D[5] += g2*(0.25f*g2+1.25f);
    }
}

// D -= Uj^T (Ij Uj); B -= Uj^T (Ij Bj)   (left neighbor, pre-inverted)
__device__ __forceinline__ void apply_left(float D[6], float B[3],
        const float I[6], const float Uj[9], const float Bj[3])
{
    float T00=I[0]*Uj[0]+I[1]*Uj[3]+I[2]*Uj[6], T01=I[0]*Uj[1]+I[1]*Uj[4]+I[2]*Uj[7], T02=I[0]*Uj[2]+I[1]*Uj[5]+I[2]*Uj[8];
    float T10=I[1]*Uj[0]+I[3]*Uj[3]+I[4]*Uj[6], T11=I[1]*Uj[1]+I[3]*Uj[4]+I[4]*Uj[7], T12=I[1]*Uj[2]+I[3]*Uj[5]+I[4]*Uj[8];
    float T20=I[2]*Uj[0]+I[4]*Uj[3]+I[5]*Uj[6], T21=I[2]*Uj[1]+I[4]*Uj[4]+I[5]*Uj[7], T22=I[2]*Uj[2]+I[4]*Uj[5]+I[5]*Uj[8];
    D[0] -= Uj[0]*T00 + Uj[3]*T10 + Uj[6]*T20;
    D[1] -= Uj[0]*T01 + Uj[3]*T11 + Uj[6]*T21;
    D[2] -= Uj[0]*T02 + Uj[3]*T12 + Uj[6]*T22;
    D[3] -= Uj[1]*T01 + Uj[4]*T11 + Uj[7]*T21;
    D[4] -= Uj[1]*T02 + Uj[4]*T12 + Uj[7]*T22;
    D[5] -= Uj[2]*T02 + Uj[5]*T12 + Uj[8]*T22;
    float v0=I[0]*Bj[0]+I[1]*Bj[1]+I[2]*Bj[2];
    float v1=I[1]*Bj[0]+I[3]*Bj[1]+I[4]*Bj[2];
    float v2=I[2]*Bj[0]+I[4]*Bj[1]+I[5]*Bj[2];
    B[0] -= Uj[0]*v0 + Uj[3]*v1 + Uj[6]*v2;
    B[1] -= Uj[1]*v0 + Uj[4]*v1 + Uj[7]*v2;
    B[2] -= Uj[2]*v0 + Uj[5]*v1 + Uj[8]*v2;
}

// P = U Ij; D -= P U^T; B -= P Bj; U' = -P Uj (iff newU)   (right neighbor)
__device__ __forceinline__ void apply_right(float D[6], float U[9], float B[3],
        const float I[6], const float Uj[9], const float Bj[3], bool newU)
{
    float P00=U[0]*I[0]+U[1]*I[1]+U[2]*I[2], P01=U[0]*I[1]+U[1]*I[3]+U[2]*I[4], P02=U[0]*I[2]+U[1]*I[4]+U[2]*I[5];
    float P10=U[3]*I[0]+U[4]*I[1]+U[5]*I[2], P11=U[3]*I[1]+U[4]*I[3]+U[5]*I[4], P12=U[3]*I[2]+U[4]*I[4]+U[5]*I[5];
    float P20=U[6]*I[0]+U[7]*I[1]+U[8]*I[2], P21=U[6]*I[1]+U[7]*I[3]+U[8]*I[4], P22=U[6]*I[2]+U[7]*I[4]+U[8]*I[5];
    D[0] -= P00*U[0] + P01*U[1] + P02*U[2];
    D[1] -= P00*U[3] + P01*U[4] + P02*U[5];
    D[2] -= P00*U[6] + P01*U[7] + P02*U[8];
    D[3] -= P10*U[3] + P11*U[4] + P12*U[5];
    D[4] -= P10*U[6] + P11*U[7] + P12*U[8];
    D[5] -= P20*U[6] + P21*U[7] + P22*U[8];
    B[0] -= P00*Bj[0] + P01*Bj[1] + P02*Bj[2];
    B[1] -= P10*Bj[0] + P11*Bj[1] + P12*Bj[2];
    B[2] -= P20*Bj[0] + P21*Bj[1] + P22*Bj[2];
    if (newU) {
        float N0 = -(P00*Uj[0] + P01*Uj[3] + P02*Uj[6]);
        float N1 = -(P00*Uj[1] + P01*Uj[4] + P02*Uj[7]);
        float N2 = -(P00*Uj[2] + P01*Uj[5] + P02*Uj[8]);
        float N3 = -(P10*Uj[0] + P11*Uj[3] + P12*Uj[6]);
        float N4 = -(P10*Uj[1] + P11*Uj[4] + P12*Uj[7]);
        float N5 = -(P10*Uj[2] + P11*Uj[5] + P12*Uj[8]);
        float N6 = -(P20*Uj[0] + P21*Uj[3] + P22*Uj[6]);
        float N7 = -(P20*Uj[1] + P21*Uj[4] + P22*Uj[7]);
        float N8 = -(P20*Uj[2] + P21*Uj[5] + P22*Uj[8]);
        U[0]=N0; U[1]=N1; U[2]=N2; U[3]=N3; U[4]=N4; U[5]=N5; U[6]=N6; U[7]=N7; U[8]=N8;
    }
}

// Published record per node: D(6), I(6), U(9), B(3) in 7 float4 slots.
struct Shm {
    float4 x0[NT];  // D0,D1,D2,D3
    float4 x1[NT];  // D4,D5,B0,B1
    float4 x2[NT];  // I0,I1,I2,I3
    float4 x3[NT];  // I4,I5,B2,pad
    float4 u0[NT];  // U0..U3
    float4 u1[NT];  // U4..U7
    float4 u2[NT];  // U8,pad,pad,pad
};

__device__ __forceinline__ void load_nb(const Shm& s, int j, float I[6], float U[9], float B[3]) {
    float4 x1=s.x1[j], x2=s.x2[j], x3=s.x3[j], a=s.u0[j], b=s.u1[j], c=s.u2[j];
    I[0]=x2.x; I[1]=x2.y; I[2]=x2.z; I[3]=x2.w; I[4]=x3.x; I[5]=x3.y;
    B[0]=x1.z; B[1]=x1.w; B[2]=x3.z;
    U[0]=a.x; U[1]=a.y; U[2]=a.z; U[3]=a.w; U[4]=b.x; U[5]=b.y; U[6]=b.z; U[7]=b.w; U[8]=c.x;
}

__device__ __forceinline__ void load_own(const Shm& s, int j, float D[6], float U[9], float B[3]) {
    float4 x0=s.x0[j], x1=s.x1[j], x3=s.x3[j], a=s.u0[j], b=s.u1[j], c=s.u2[j];
    D[0]=x0.x; D[1]=x0.y; D[2]=x0.z; D[3]=x0.w; D[4]=x1.x; D[5]=x1.y;
    B[0]=x1.z; B[1]=x1.w; B[2]=x3.z;
    U[0]=a.x; U[1]=a.y; U[2]=a.z; U[3]=a.w; U[4]=b.x; U[5]=b.y; U[6]=b.z; U[7]=b.w; U[8]=c.x;
}

__device__ __forceinline__ void publish(Shm& s, int t, const float D[6], const float U[9], const float B[3]) {
    float I[6]; inv3_sym(D, I);
    s.x0[t] = make_float4(D[0],D[1],D[2],D[3]);
    s.x1[t] = make_float4(D[4],D[5],B[0],B[1]);
    s.x2[t] = make_float4(I[0],I[1],I[2],I[3]);
    s.x3[t] = make_float4(I[4],I[5],B[2],0.0f);
    s.u0[t] = make_float4(U[0],U[1],U[2],U[3]);
    s.u1[t] = make_float4(U[4],U[5],U[6],U[7]);
    s.u2[t] = make_float4(U[8],0.0f,0.0f,0.0f);
}

// One fused phase: applies PCR levels with strides S and 2S to (D,U,B) of node t.
template<int S>
__device__ __forceinline__ void fused_phase(const Shm& cur, int t, float D[6], float U[9], float B[3]) {
    const bool hasL = (t - 2*S) >= 0;
    const bool hasR = (t + 2*S) <= 99;

    float LD[6], LU[9], LB[3];
    float NI[6], NU[9], NB[3];   // rotating neighbor record

    // ---- left side: L = state at t-2S, sub-updated; own left sub-update ----
    if (hasL) {
        load_own(cur, t - 2*S, LD, LU, LB);
        if (t - 3*S >= 0) {
            load_nb(cur, t - 3*S, NI, NU, NB);
            apply_left(LD, LB, NI, NU, NB);
        }
    }
    if (t - S >= 0) {
        load_nb(cur, t - S, NI, NU, NB);
        if (hasL) apply_right(LD, LU, LB, NI, NU, NB, true);  // (t-2S)+2S = t <= 99
        apply_left(D, B, NI, NU, NB);
    }
    // ---- right side ----
    float RD[6], RU[9], RB[3];
    if (t + S <= 99) {
        load_nb(cur, t + S, NI, NU, NB);
        apply_right(D, U, B, NI, NU, NB, hasR);
        if (hasR) {
            load_own(cur, t + 2*S, RD, RU, RB);
            apply_left(RD, RB, NI, NU, NB);
            if (t + 3*S <= 99) {
                load_nb(cur, t + 3*S, NI, NU, NB);
                apply_right(RD, RU, RB, NI, NU, NB, (t + 4*S) <= 99);
            }
        }
    }
    // ---- second level (stride 2S) in registers ----
    if (hasL) {
        float IL[6]; inv3_sym(LD, IL);
        apply_left(D, B, IL, LU, LB);
    }
    if (hasR) {
        float IR[6]; inv3_sym(RD, IR);
        apply_right(D, U, B, IR, RU, RB, (t + 4*S) <= 99);
    }
}

__global__ __launch_bounds__(128)
void ode_pcr_r4_kernel(const float* __restrict__ coeffs,
                       const float* __restrict__ rhs,
                       const float* __restrict__ iv_rhs,
                       const float* __restrict__ steps,
                       float* __restrict__ out)
{
    __shared__ Shm shm[2];

    const int sys = blockIdx.x;
    const int t   = threadIdx.x;

    const float* C  = coeffs + sys * 300;
    const float* R  = rhs    + sys * 100;
    const float* IV = iv_rhs + sys * 2;
    const float* ST = steps  + sys * 99;

    float st_local = 0.0f;
    float D[6], U[9], B[3];

    // ---------------- fused build + level 0 (s=1), registers ----------------
    if (t < NT) {
        if (t < 99) st_local = ST[t];
        build_node(t, C, R, IV, ST, D, U, B);
        if (t >= 1) {
            float Dl[6], Ul[9], Bl[3];
            build_node(t-1, C, R, IV, ST, Dl, Ul, Bl);
            float Il[6]; inv3_sym(Dl, Il);
            apply_left(D, B, Il, Ul, Bl);
        }
        if (t + 1 <= 99) {
            float Dr[6], Ur[9], Br[3];
            build_node(t+1, C, R, IV, ST, Dr, Ur, Br);
            float Ir[6]; inv3_sym(Dr, Ir);
            apply_right(D, U, B, Ir, Ur, Br, (t + 2 <= 99));
        }
        publish(shm[0], t, D, U, B);   // state_1
    }
    __syncthreads();

    // ---------------- 3 fused phases: levels (1,2), (3,4), (5,6) ----------------
    if (t < NT) fused_phase<2>(shm[0], t, D, U, B);   // -> state_3
    if (t < NT) publish(shm[1], t, D, U, B);
    __syncthreads();

    if (t < NT) fused_phase<8>(shm[1], t, D, U, B);   // -> state_5
    if (t < NT) publish(shm[0], t, D, U, B);
    __syncthreads();

    if (t < NT) fused_phase<32>(shm[0], t, D, U, B);  // -> state_7 (decoupled)

    // ---------------- diagonal solve + outputs ----------------
    if (t < NT) {
        float I[6]; inv3_sym(D, I);
        float x0 = I[0]*B[0] + I[1]*B[1] + I[2]*B[2];
        float x1 = I[1]*B[0] + I[3]*B[1] + I[4]*B[2];
        float x2 = I[2]*B[0] + I[4]*B[1] + I[5]*B[2];
        out[        sys*100 + t] = x0;
        out[25600 + sys*100 + t] = x1;
        out[51200 + sys*100 + t] = x2;
    }
    if (t == 0) out[76800 + sys] = 0.0f;
    if (t < 99) out[77056 + sys*99 + t] = st_local;
}

extern "C" void kernel_launch(void* const* d_in, const int* in_sizes, int n_in,
                              void* d_out, int out_size)
{
    (void)out_size;
    const float* coeffs = nullptr;
    const float* rhs    = nullptr;
    const float* iv_rhs = nullptr;
    const float* steps  = nullptr;
    for (int i = 0; i < n_in; ++i) {
        switch (in_sizes[i]) {
            case 76800: coeffs = (const float*)d_in[i]; break;
            case 25600: rhs    = (const float*)d_in[i]; break;
            case 512:   iv_rhs = (const float*)d_in[i]; break;
            case 25344: steps  = (const float*)d_in[i]; break;
            default: break;
        }
    }
    if (!coeffs && n_in > 0) coeffs = (const float*)d_in[0];
    if (!rhs    && n_in > 1) rhs    = (const float*)d_in[1];
    if (!iv_rhs && n_in > 2) iv_rhs = (const float*)d_in[2];
    if (!steps  && n_in > 3) steps  = (const float*)d_in[3];

    ode_pcr_r4_kernel<<<NSYS, 128>>>(coeffs, rhs, iv_rhs, steps, (float*)d_out);
}

// round 12
// speedup vs baseline: 1.2574x; 1.2574x over previous
#include <cuda_runtime.h>

// ODEINDLayer: 256 independent SPD block-tridiagonal systems (100 blocks of
// 3x3). PCR with TWO NODES PER THREAD packed in f32x2 (sm_103a packed FMA):
// nodes (2p, 2p+1) share one 64-bit lane pair. Level s=1 fused in scalar
// registers at build; levels s=2..64 (pair-strides 1..32) run fully packed,
// one barrier per level. 50 active threads per system, one CTA per system.

#define NSYS 256

typedef unsigned long long u64;
typedef unsigned int u32;

// ---------------- f32x2 packed helpers ----------------
__device__ __forceinline__ u64 pack2(float lo, float hi) {
    u32 a = __float_as_uint(lo), b = __float_as_uint(hi);
    u64 r; asm("mov.b64 %0, {%1, %2};" : "=l"(r) : "r"(a), "r"(b)); return r;
}
__device__ __forceinline__ void unpack2(u64 v, float& lo, float& hi) {
    u32 a, b; asm("mov.b64 {%0, %1}, %2;" : "=r"(a), "=r"(b) : "l"(v));
    lo = __uint_as_float(a); hi = __uint_as_float(b);
}
__device__ __forceinline__ u64 fma2(u64 a, u64 b, u64 c) {
    u64 d; asm("fma.rn.f32x2 %0, %1, %2, %3;" : "=l"(d) : "l"(a), "l"(b), "l"(c)); return d;
}
__device__ __forceinline__ u64 mul2(u64 a, u64 b) {
    u64 d; asm("mul.rn.f32x2 %0, %1, %2;" : "=l"(d) : "l"(a), "l"(b)); return d;
}
__device__ __forceinline__ u64 neg2(u64 a) { return a ^ 0x8000000080000000ULL; }

__device__ __forceinline__ float frcp_nr(float x) {
    float r; asm("rcp.approx.f32 %0, %1;" : "=f"(r) : "f"(x));
    return r * (2.0f - x * r);
}

// Packed inverse of symmetric 3x3 (00,01,02,11,12,22), both lanes at once.
__device__ __forceinline__ void inv3_sym2(const u64 M[6], u64 I[6]) {
    u64 A00 = fma2(M[3], M[5], neg2(mul2(M[4], M[4])));
    u64 A01 = fma2(M[2], M[4], neg2(mul2(M[1], M[5])));
    u64 A02 = fma2(M[1], M[4], neg2(mul2(M[2], M[3])));
    u64 A11 = fma2(M[0], M[5], neg2(mul2(M[2], M[2])));
    u64 A12 = fma2(M[1], M[2], neg2(mul2(M[0], M[4])));
    u64 A22 = fma2(M[0], M[3], neg2(mul2(M[1], M[1])));
    u64 det = fma2(M[2], A02, fma2(M[1], A01, mul2(M[0], A00)));
    float dl, dh; unpack2(det, dl, dh);
    float rl, rh;
    asm("rcp.approx.f32 %0, %1;" : "=f"(rl) : "f"(dl));
    asm("rcp.approx.f32 %0, %1;" : "=f"(rh) : "f"(dh));
    u64 r = pack2(rl, rh);
    const u64 two = 0x4000000040000000ULL;
    r = mul2(r, fma2(neg2(det), r, two));     // Newton step
    I[0]=mul2(A00,r); I[1]=mul2(A01,r); I[2]=mul2(A02,r);
    I[3]=mul2(A11,r); I[4]=mul2(A12,r); I[5]=mul2(A22,r);
}

// Packed left elimination: D -= Uj^T (Ij Uj); B -= Uj^T (Ij Bj).
__device__ __forceinline__ void apply_left2(u64 D[6], u64 B[3],
        const u64 I[6], const u64 U[9], const u64 Bj[3])
{
    u64 T00=fma2(I[2],U[6],fma2(I[1],U[3],mul2(I[0],U[0])));
    u64 T01=fma2(I[2],U[7],fma2(I[1],U[4],mul2(I[0],U[1])));
    u64 T02=fma2(I[2],U[8],fma2(I[1],U[5],mul2(I[0],U[2])));
    u64 T10=fma2(I[4],U[6],fma2(I[3],U[3],mul2(I[1],U[0])));
    u64 T11=fma2(I[4],U[7],fma2(I[3],U[4],mul2(I[1],U[1])));
    u64 T12=fma2(I[4],U[8],fma2(I[3],U[5],mul2(I[1],U[2])));
    u64 T20=fma2(I[5],U[6],fma2(I[4],U[3],mul2(I[2],U[0])));
    u64 T21=fma2(I[5],U[7],fma2(I[4],U[4],mul2(I[2],U[1])));
    u64 T22=fma2(I[5],U[8],fma2(I[4],U[5],mul2(I[2],U[2])));
    u64 n0=neg2(U[0]), n1=neg2(U[1]), n2=neg2(U[2]);
    u64 n3=neg2(U[3]), n4=neg2(U[4]), n5=neg2(U[5]);
    u64 n6=neg2(U[6]), n7=neg2(U[7]), n8=neg2(U[8]);
    D[0]=fma2(n6,T20,fma2(n3,T10,fma2(n0,T00,D[0])));
    D[1]=fma2(n6,T21,fma2(n3,T11,fma2(n0,T01,D[1])));
    D[2]=fma2(n6,T22,fma2(n3,T12,fma2(n0,T02,D[2])));
    D[3]=fma2(n7,T21,fma2(n4,T11,fma2(n1,T01,D[3])));
    D[4]=fma2(n7,T22,fma2(n4,T12,fma2(n1,T02,D[4])));
    D[5]=fma2(n8,T22,fma2(n5,T12,fma2(n2,T02,D[5])));
    u64 v0=fma2(I[2],Bj[2],fma2(I[1],Bj[1],mul2(I[0],Bj[0])));
    u64 v1=fma2(I[4],Bj[2],fma2(I[3],Bj[1],mul2(I[1],Bj[0])));
    u64 v2=fma2(I[5],Bj[2],fma2(I[4],Bj[1],mul2(I[2],Bj[0])));
    B[0]=fma2(n6,v2,fma2(n3,v1,fma2(n0,v0,B[0])));
    B[1]=fma2(n7,v2,fma2(n4,v1,fma2(n1,v0,B[1])));
    B[2]=fma2(n8,v2,fma2(n5,v1,fma2(n2,v0,B[2])));
}

// Packed right elimination: P=U Ij; D-=P U^T; B-=P Bj; U'=-P Uj (iff newU).
__device__ __forceinline__ void apply_right2(u64 D[6], u64 U[9], u64 B[3],
        const u64 I[6], const u64 Uj[9], const u64 Bj[3], bool newU)
{
    u64 P00=fma2(U[2],I[2],fma2(U[1],I[1],mul2(U[0],I[0])));
    u64 P01=fma2(U[2],I[4],fma2(U[1],I[3],mul2(U[0],I[1])));
    u64 P02=fma2(U[2],I[5],fma2(U[1],I[4],mul2(U[0],I[2])));
    u64 P10=fma2(U[5],I[2],fma2(U[4],I[1],mul2(U[3],I[0])));
    u64 P11=fma2(U[5],I[4],fma2(U[4],I[3],mul2(U[3],I[1])));
    u64 P12=fma2(U[5],I[5],fma2(U[4],I[4],mul2(U[3],I[2])));
    u64 P20=fma2(U[8],I[2],fma2(U[7],I[1],mul2(U[6],I[0])));
    u64 P21=fma2(U[8],I[4],fma2(U[7],I[3],mul2(U[6],I[1])));
    u64 P22=fma2(U[8],I[5],fma2(U[7],I[4],mul2(U[6],I[2])));
    u64 m00=neg2(P00), m01=neg2(P01), m02=neg2(P02);
    u64 m10=neg2(P10), m11=neg2(P11), m12=neg2(P12);
    u64 m20=neg2(P20), m21=neg2(P21), m22=neg2(P22);
    D[0]=fma2(m02,U[2],fma2(m01,U[1],fma2(m00,U[0],D[0])));
    D[1]=fma2(m02,U[5],fma2(m01,U[4],fma2(m00,U[3],D[1])));
    D[2]=fma2(m02,U[8],fma2(m01,U[7],fma2(m00,U[6],D[2])));
    D[3]=fma2(m12,U[5],fma2(m11,U[4],fma2(m10,U[3],D[3])));
    D[4]=fma2(m12,U[8],fma2(m11,U[7],fma2(m10,U[6],D[4])));
    D[5]=fma2(m22,U[8],fma2(m21,U[7],fma2(m20,U[6],D[5])));
    B[0]=fma2(m02,Bj[2],fma2(m01,Bj[1],fma2(m00,Bj[0],B[0])));
    B[1]=fma2(m12,Bj[2],fma2(m11,Bj[1],fma2(m10,Bj[0],B[1])));
    B[2]=fma2(m22,Bj[2],fma2(m21,Bj[1],fma2(m20,Bj[0],B[2])));
    if (newU) {
        U[0]=fma2(m02,Uj[6],fma2(m01,Uj[3],mul2(m00,Uj[0])));
        U[1]=fma2(m02,Uj[7],fma2(m01,Uj[4],mul2(m00,Uj[1])));
        U[2]=fma2(m02,Uj[8],fma2(m01,Uj[5],mul2(m00,Uj[2])));
        U[3]=fma2(m12,Uj[6],fma2(m11,Uj[3],mul2(m10,Uj[0])));
        U[4]=fma2(m12,Uj[7],fma2(m11,Uj[4],mul2(m10,Uj[1])));
        U[5]=fma2(m12,Uj[8],fma2(m11,Uj[5],mul2(m10,Uj[2])));
        U[6]=fma2(m22,Uj[6],fma2(m21,Uj[3],mul2(m20,Uj[0])));
        U[7]=fma2(m22,Uj[7],fma2(m21,Uj[4],mul2(m20,Uj[1])));
        U[8]=fma2(m22,Uj[8],fma2(m21,Uj[5],mul2(m20,Uj[2])));
    }
}

// ---------------- scalar helpers for the fused build + s=1 level ----------------
__device__ __forceinline__ void inv3_sym(const float M[6], float I[6]) {
    float A00 = M[3]*M[5] - M[4]*M[4];
    float A01 = M[2]*M[4] - M[1]*M[5];
    float A02 = M[1]*M[4] - M[2]*M[3];
    float A11 = M[0]*M[5] - M[2]*M[2];
    float A12 = M[1]*M[2] - M[0]*M[4];
    float A22 = M[0]*M[3] - M[1]*M[1];
    float id  = frcp_nr(M[0]*A00 + M[1]*A01 + M[2]*A02);
    I[0]=A00*id; I[1]=A01*id; I[2]=A02*id; I[3]=A11*id; I[4]=A12*id; I[5]=A22*id;
}

__device__ __forceinline__ void build_node(int i,
        const float* __restrict__ C, const float* __restrict__ R,
        const float* __restrict__ IV, const float* __restrict__ ST,
        float D[6], float U[9], float B[3])
{
    float c0 = C[3*i], c1 = C[3*i+1], c2 = C[3*i+2];
    float rt = R[i];
    D[0]=c0*c0; D[1]=c0*c1; D[2]=c0*c2; D[3]=c1*c1; D[4]=c1*c2; D[5]=c2*c2;
    B[0]=c0*rt; B[1]=c1*rt; B[2]=c2*rt;
    if (i == 0) { D[0] += 1.0f; D[3] += 1.0f; B[0] += IV[0]; B[1] += IV[1]; }
    if (i < 99) {
        float h = ST[i], h2 = h*h;
        D[0] += 2.0f;      D[1] += h;                D[2] += 0.5f*h2;
        D[3] += h2+3.0f;   D[4] += h*(0.5f*h2+1.5f); D[5] += h2*(0.25f*h2+1.25f);
        U[0]=-2.0f;    U[1]=h;       U[2]=-0.5f*h2;
        U[3]=-h;       U[4]=-3.0f;   U[5]=1.5f*h;
        U[6]=-0.5f*h2; U[7]=-1.5f*h; U[8]=0.25f*h2;
    } else {
        #pragma unroll
        for (int k = 0; k < 9; ++k) U[k] = 0.0f;
    }
    if (i >= 1) {
        float g = ST[i-1], g2 = g*g;
        D[0] += 2.0f;      D[1] -= g;                D[2] += 0.5f*g2;
        D[3] += g2+3.0f;   D[4] -= g*(0.5f*g2+1.5f); D[5] += g2*(0.25f*g2+1.25f);
    }
}

__device__ __forceinline__ void apply_left(float D[6], float B[3],
        const float I[6], const float Uj[9], const float Bj[3])
{
    float T00=I[0]*Uj[0]+I[1]*Uj[3]+I[2]*Uj[6], T01=I[0]*Uj[1]+I[1]*Uj[4]+I[2]*Uj[7], T02=I[0]*Uj[2]+I[1]*Uj[5]+I[2]*Uj[8];
    float T10=I[1]*Uj[0]+I[3]*Uj[3]+I[4]*Uj[6], T11=I[1]*Uj[1]+I[3]*Uj[4]+I[4]*Uj[7], T12=I[1]*Uj[2]+I[3]*Uj[5]+I[4]*Uj[8];
    float T20=I[2]*Uj[0]+I[4]*Uj[3]+I[5]*Uj[6], T21=I[2]*Uj[1]+I[4]*Uj[4]+I[5]*Uj[7], T22=I[2]*Uj[2]+I[4]*Uj[5]+I[5]*Uj[8];
    D[0] -= Uj[0]*T00 + Uj[3]*T10 + Uj[6]*T20;
    D[1] -= Uj[0]*T01 + Uj[3]*T11 + Uj[6]*T21;
    D[2] -= Uj[0]*T02 + Uj[3]*T12 + Uj[6]*T22;
    D[3] -= Uj[1]*T01 + Uj[4]*T11 + Uj[7]*T21;
    D[4] -= Uj[1]*T02 + Uj[4]*T12 + Uj[7]*T22;
    D[5] -= Uj[2]*T02 + Uj[5]*T12 + Uj[8]*T22;
    float v0=I[0]*Bj[0]+I[1]*Bj[1]+I[2]*Bj[2];
    float v1=I[1]*Bj[0]+I[3]*Bj[1]+I[4]*Bj[2];
    float v2=I[2]*Bj[0]+I[4]*Bj[1]+I[5]*Bj[2];
    B[0] -= Uj[0]*v0 + Uj[3]*v1 + Uj[6]*v2;
    B[1] -= Uj[1]*v0 + Uj[4]*v1 + Uj[7]*v2;
    B[2] -= Uj[2]*v0 + Uj[5]*v1 + Uj[8]*v2;
}

__device__ __forceinline__ void apply_right(float D[6], float U[9], float B[3],
        const float I[6], const float Uj[9], const float Bj[3], bool newU)
{
    float P00=U[0]*I[0]+U[1]*I[1]+U[2]*I[2], P01=U[0]*I[1]+U[1]*I[3]+U[2]*I[4], P02=U[0]*I[2]+U[1]*I[4]+U[2]*I[5];
    float P10=U[3]*I[0]+U[4]*I[1]+U[5]*I[2], P11=U[3]*I[1]+U[4]*I[3]+U[5]*I[4], P12=U[3]*I[2]+U[4]*I[4]+U[5]*I[5];
    float P20=U[6]*I[0]+U[7]*I[1]+U[8]*I[2], P21=U[6]*I[1]+U[7]*I[3]+U[8]*I[4], P22=U[6]*I[2]+U[7]*I[4]+U[8]*I[5];
    D[0] -= P00*U[0] + P01*U[1] + P02*U[2];
    D[1] -= P00*U[3] + P01*U[4] + P02*U[5];
    D[2] -= P00*U[6] + P01*U[7] + P02*U[8];
    D[3] -= P10*U[3] + P11*U[4] + P12*U[5];
    D[4] -= P10*U[6] + P11*U[7] + P12*U[8];
    D[5] -= P20*U[6] + P21*U[7] + P22*U[8];
    B[0] -= P00*Bj[0] + P01*Bj[1] + P02*Bj[2];
    B[1] -= P10*Bj[0] + P11*Bj[1] + P12*Bj[2];
    B[2] -= P20*Bj[0] + P21*Bj[1] + P22*Bj[2];
    if (newU) {
        float N0 = -(P00*Uj[0] + P01*Uj[3] + P02*Uj[6]);
        float N1 = -(P00*Uj[1] + P01*Uj[4] + P02*Uj[7]);
        float N2 = -(P00*Uj[2] + P01*Uj[5] + P02*Uj[8]);
        float N3 = -(P10*Uj[0] + P11*Uj[3] + P12*Uj[6]);
        float N4 = -(P10*Uj[1] + P11*Uj[4] + P12*Uj[7]);
        float N5 = -(P10*Uj[2] + P11*Uj[5] + P12*Uj[8]);
        float N6 = -(P20*Uj[0] + P21*Uj[3] + P22*Uj[6]);
        float N7 = -(P20*Uj[1] + P21*Uj[4] + P22*Uj[7]);
        float N8 = -(P20*Uj[2] + P21*Uj[5] + P22*Uj[8]);
        U[0]=N0; U[1]=N1; U[2]=N2; U[3]=N3; U[4]=N4; U[5]=N5; U[6]=N6; U[7]=N7; U[8]=N8;
    }
}

// ---------------- kernel ----------------
__global__ __launch_bounds__(64)
void ode_pcr_x2_kernel(const float* __restrict__ coeffs,
                       const float* __restrict__ rhs,
                       const float* __restrict__ iv_rhs,
                       const float* __restrict__ steps,
                       float* __restrict__ out)
{
    // Published pair record: I(6) U(9) B(3) packed u64 -> 9 ulonglong2 slots.
    __shared__ ulonglong2 sR[2][9][52];

    const int sys = blockIdx.x;
    const int p   = threadIdx.x;          // pair index; nodes 2p, 2p+1

    const float* C  = coeffs + sys * 300;
    const float* R  = rhs    + sys * 100;
    const float* IV = iv_rhs + sys * 2;
    const float* ST = steps  + sys * 99;

    u64 D[6], U[9], B[3];

    // -------- fused build + node-stride-1 level (scalar), then pack --------
    if (p < 50) {
        const int n0 = 2*p;
        float Xd[4][6], Xu[4][9], Xb[4][3];   // nodes n0-1, n0, n0+1, n0+2
        if (p >= 1)  build_node(n0-1, C, R, IV, ST, Xd[0], Xu[0], Xb[0]);
        build_node(n0,   C, R, IV, ST, Xd[1], Xu[1], Xb[1]);
        build_node(n0+1, C, R, IV, ST, Xd[2], Xu[2], Xb[2]);
        if (p <= 48) build_node(n0+2, C, R, IV, ST, Xd[3], Xu[3], Xb[3]);

        float Da[6], Ua[9], Ba[3], Db[6], Ub[9], Bb[3];
        #pragma unroll
        for (int k = 0; k < 6; ++k) { Da[k]=Xd[1][k]; Db[k]=Xd[2][k]; }
        #pragma unroll
        for (int k = 0; k < 9; ++k) { Ua[k]=Xu[1][k]; Ub[k]=Xu[2][k]; }
        #pragma unroll
        for (int k = 0; k < 3; ++k) { Ba[k]=Xb[1][k]; Bb[k]=Xb[2][k]; }

        // node 2p: left = 2p-1 (if any), right = 2p+1
        if (p >= 1) {
            float I0[6]; inv3_sym(Xd[0], I0);
            apply_left(Da, Ba, I0, Xu[0], Xb[0]);
        }
        { float I2[6]; inv3_sym(Xd[2], I2);
          apply_right(Da, Ua, Ba, I2, Xu[2], Xb[2], p <= 48); }
        // node 2p+1: left = 2p, right = 2p+2 (if any)
        { float I1[6]; inv3_sym(Xd[1], I1);
          apply_left(Db, Bb, I1, Xu[1], Xb[1]); }
        if (p <= 48) {
            float I3[6]; inv3_sym(Xd[3], I3);
            apply_right(Db, Ub, Bb, I3, Xu[3], Xb[3], p <= 48);
        }

        #pragma unroll
        for (int k = 0; k < 6; ++k) D[k] = pack2(Da[k], Db[k]);
        #pragma unroll
        for (int k = 0; k < 9; ++k) U[k] = pack2(Ua[k], Ub[k]);
        #pragma unroll
        for (int k = 0; k < 3; ++k) B[k] = pack2(Ba[k], Bb[k]);

        // publish pair record (own inverse computed once)
        u64 I[6]; inv3_sym2(D, I);
        sR[0][0][p]=make_ulonglong2(I[0],I[1]); sR[0][1][p]=make_ulonglong2(I[2],I[3]);
        sR[0][2][p]=make_ulonglong2(I[4],I[5]); sR[0][3][p]=make_ulonglong2(U[0],U[1]);
        sR[0][4][p]=make_ulonglong2(U[2],U[3]); sR[0][5][p]=make_ulonglong2(U[4],U[5]);
        sR[0][6][p]=make_ulonglong2(U[6],U[7]); sR[0][7][p]=make_ulonglong2(U[8],B[0]);
        sR[0][8][p]=make_ulonglong2(B[1],B[2]);
    }
    __syncthreads();

    // -------- 6 packed PCR levels, pair-strides 1..32 --------
    #pragma unroll
    for (int l = 0; l < 6; ++l) {
        const int sg  = 1 << l;
        const int cur = l & 1;

        if (p < 50) {
            u64 NI[6], NU[9], NB[3];
            if (p >= sg) {
                const int j = p - sg;
                ulonglong2 a0=sR[cur][0][j], a1=sR[cur][1][j], a2=sR[cur][2][j];
                ulonglong2 a3=sR[cur][3][j], a4=sR[cur][4][j], a5=sR[cur][5][j];
                ulonglong2 a6=sR[cur][6][j], a7=sR[cur][7][j], a8=sR[cur][8][j];
                NI[0]=a0.x; NI[1]=a0.y; NI[2]=a1.x; NI[3]=a1.y; NI[4]=a2.x; NI[5]=a2.y;
                NU[0]=a3.x; NU[1]=a3.y; NU[2]=a4.x; NU[3]=a4.y; NU[4]=a5.x; NU[5]=a5.y;
                NU[6]=a6.x; NU[7]=a6.y; NU[8]=a7.x; NB[0]=a7.y; NB[1]=a8.x; NB[2]=a8.y;
                apply_left2(D, B, NI, NU, NB);
            }
            if (p + sg <= 49) {
                const int j = p + sg;
                ulonglong2 a0=sR[cur][0][j], a1=sR[cur][1][j], a2=sR[cur][2][j];
                ulonglong2 a3=sR[cur][3][j], a4=sR[cur][4][j], a5=sR[cur][5][j];
                ulonglong2 a6=sR[cur][6][j], a7=sR[cur][7][j], a8=sR[cur][8][j];
                NI[0]=a0.x; NI[1]=a0.y; NI[2]=a1.x; NI[3]=a1.y; NI[4]=a2.x; NI[5]=a2.y;
                NU[0]=a3.x; NU[1]=a3.y; NU[2]=a4.x; NU[3]=a4.y; NU[4]=a5.x; NU[5]=a5.y;
                NU[6]=a6.x; NU[7]=a6.y; NU[8]=a7.x; NB[0]=a7.y; NB[1]=a8.x; NB[2]=a8.y;
                apply_right2(D, U, B, NI, NU, NB, (p + 2*sg <= 49));
            }
        }
        if (l < 5) {
            if (p < 50) {
                const int nb = cur ^ 1;
                u64 I[6]; inv3_sym2(D, I);
                sR[nb][0][p]=make_ulonglong2(I[0],I[1]); sR[nb][1][p]=make_ulonglong2(I[2],I[3]);
                sR[nb][2][p]=make_ulonglong2(I[4],I[5]); sR[nb][3][p]=make_ulonglong2(U[0],U[1]);
                sR[nb][4][p]=make_ulonglong2(U[2],U[3]); sR[nb][5][p]=make_ulonglong2(U[4],U[5]);
                sR[nb][6][p]=make_ulonglong2(U[6],U[7]); sR[nb][7][p]=make_ulonglong2(U[8],B[0]);
                sR[nb][8][p]=make_ulonglong2(B[1],B[2]);
            }
            __syncthreads();
        }
    }

    // -------- diagonal solve per node + outputs --------
    if (p < 50) {
        float Ma[6], Mb[6], ba[3], bb[3];
        #pragma unroll
        for (int k = 0; k < 6; ++k) unpack2(D[k], Ma[k], Mb[k]);
        #pragma unroll
        for (int k = 0; k < 3; ++k) unpack2(B[k], ba[k], bb[k]);

        float Ia[6]; inv3_sym(Ma, Ia);
        float Ib[6]; inv3_sym(Mb, Ib);
        int n0 = 2*p, n1 = 2*p + 1;
        out[        sys*100 + n0] = Ia[0]*ba[0] + Ia[1]*ba[1] + Ia[2]*ba[2];
        out[25600 + sys*100 + n0] = Ia[1]*ba[0] + Ia[3]*ba[1] + Ia[4]*ba[2];
        out[51200 + sys*100 + n0] = Ia[2]*ba[0] + Ia[4]*ba[1] + Ia[5]*ba[2];
        out[        sys*100 + n1] = Ib[0]*bb[0] + Ib[1]*bb[1] + Ib[2]*bb[2];
        out[25600 + sys*100 + n1] = Ib[1]*bb[0] + Ib[3]*bb[1] + Ib[4]*bb[2];
        out[51200 + sys*100 + n1] = Ib[2]*bb[0] + Ib[4]*bb[1] + Ib[5]*bb[2];

        if (n0 < 99) out[77056 + sys*99 + n0] = ST[n0];
        if (n1 < 99) out[77056 + sys*99 + n1] = ST[n1];
        if (p == 0)  out[76800 + sys] = 0.0f;
    }
}

extern "C" void kernel_launch(void* const* d_in, const int* in_sizes, int n_in,
                              void* d_out, int out_size)
{
    (void)out_size;
    const float* coeffs = nullptr;
    const float* rhs    = nullptr;
    const float* iv_rhs = nullptr;
    const float* steps  = nullptr;
    for (int i = 0; i < n_in; ++i) {
        switch (in_sizes[i]) {
            case 76800: coeffs = (const float*)d_in[i]; break;
            case 25600: rhs    = (const float*)d_in[i]; break;
            case 512:   iv_rhs = (const float*)d_in[i]; break;
            case 25344: steps  = (const float*)d_in[i]; break;
            default: break;
        }
    }
    if (!coeffs && n_in > 0) coeffs = (const float*)d_in[0];
    if (!rhs    && n_in > 1) rhs    = (const float*)d_in[1];
    if (!iv_rhs && n_in > 2) iv_rhs = (const float*)d_in[2];
    if (!steps  && n_in > 3) steps  = (const float*)d_in[3];

    ode_pcr_x2_kernel<<<NSYS, 64>>>(coeffs, rhs, iv_rhs, steps, (float*)d_out);
}